// round 4
// baseline (speedup 1.0000x reference)
#include <cuda_runtime.h>
#include <math.h>

#define NBOARD 13
#define SN 169          // nodes per graph
#define NG 2048         // graphs
#define NT 192          // threads per GNN block
#define EPSV 1e-5f
#define LSMIN -5.0f
#define LSMAX 2.0f

typedef unsigned long long ull;

// ---- packed f32x2 helpers ----
__device__ __forceinline__ ull pk2(float x, float y) {
    ull r; asm("mov.b64 %0, {%1,%2};" : "=l"(r) : "f"(x), "f"(y)); return r;
}
__device__ __forceinline__ float2 upk2(ull a) {
    float2 v; asm("mov.b64 {%0,%1}, %2;" : "=f"(v.x), "=f"(v.y) : "l"(a)); return v;
}
__device__ __forceinline__ ull ffma2(ull a, ull b, ull c) {
    ull d; asm("fma.rn.f32x2 %0, %1, %2, %3;" : "=l"(d) : "l"(a), "l"(b), "l"(c)); return d;
}
__device__ __forceinline__ ull fadd2(ull a, ull b) {
    ull d; asm("add.rn.f32x2 %0, %1, %2;" : "=l"(d) : "l"(a), "l"(b)); return d;
}
__device__ __forceinline__ ull fmul2(ull a, ull b) {
    ull d; asm("mul.rn.f32x2 %0, %1, %2;" : "=l"(d) : "l"(a), "l"(b)); return d;
}

__device__ float g_pooled[NG * 72];

#define HS 74            // h row stride in floats
#define HSU 37
#define TS 38            // stage row stride
#define TSU 19

struct __align__(16) Smem {
    float wc3[36 * 72];
    float wr2[36 * 72];
    float wc2[18 * 36];
    float wr1[18 * 36];
    float wc1p[18 * 20];
    float bc1[18], bc2[36], bc3[72];
    float br1[36], br2[72];
    float g1v[18], be1v[18], a1v[18];
    float g2v[36], be2v[36], a2v[36];
    float g3v[72], be3v[72], a3v[72];
    float embs[3 * 18];
    float redP[180], redQ[180];
    float redS[72], redC[72];
    float dis[170];
    float stage[SN * TS];
    float h[SN * HS];
};

__device__ __forceinline__ void cp_sm(float* dst, const float* src, int n, int t) {
    for (int i = t; i < n; i += NT) dst[i] = src[i];
}

__device__ __forceinline__ void stats_striped(Smem& sm, int t, int Wf) {
    if (t < 180) {
        const int f = t % Wf, sI = t / Wf, step = 180 / Wf;
        float s = 0.f, s2 = 0.f;
        const float* p = sm.stage + f;
        for (int n = sI; n < SN; n += step) { float v = p[n * TS]; s += v; s2 = fmaf(v, v, s2); }
        sm.redP[t] = s; sm.redQ[t] = s2;
    }
}

__global__ void __launch_bounds__(NT, 2) gnn_kernel(
    const int* __restrict__ x,
    const float* __restrict__ emb,
    const float* __restrict__ wc1, const float* __restrict__ bc1,
    const float* __restrict__ wc2, const float* __restrict__ bc2,
    const float* __restrict__ wc3, const float* __restrict__ bc3,
    const float* __restrict__ wr1, const float* __restrict__ br1,
    const float* __restrict__ wr2, const float* __restrict__ br2,
    const float* __restrict__ g1, const float* __restrict__ be1, const float* __restrict__ a1,
    const float* __restrict__ g2, const float* __restrict__ be2, const float* __restrict__ a2,
    const float* __restrict__ g3, const float* __restrict__ be3, const float* __restrict__ a3)
{
    extern __shared__ char smraw[];
    Smem& sm = *reinterpret_cast<Smem*>(smraw);
    const int t = threadIdx.x;
    const int g = blockIdx.x;
    const bool isNode = (t < SN);
    ull* const hU = (ull*)sm.h;
    ull* const stU = (ull*)sm.stage;
    const float invS = 1.0f / (float)SN;

    cp_sm(sm.wc3, wc3, 36 * 72, t);
    cp_sm(sm.wr2, wr2, 36 * 72, t);
    cp_sm(sm.wc2, wc2, 18 * 36, t);
    cp_sm(sm.wr1, wr1, 18 * 36, t);
    for (int i = t; i < 18 * 20; i += NT) {
        const int k = i / 20, j = i % 20;
        sm.wc1p[i] = (j < 18) ? wc1[k * 18 + j] : 0.f;
    }
    cp_sm(sm.bc1, bc1, 18, t);  cp_sm(sm.bc2, bc2, 36, t);  cp_sm(sm.bc3, bc3, 72, t);
    cp_sm(sm.br1, br1, 36, t);  cp_sm(sm.br2, br2, 72, t);
    cp_sm(sm.g1v, g1, 18, t);   cp_sm(sm.be1v, be1, 18, t); cp_sm(sm.a1v, a1, 18, t);
    cp_sm(sm.g2v, g2, 36, t);   cp_sm(sm.be2v, be2, 36, t); cp_sm(sm.a2v, a2, 36, t);
    cp_sm(sm.g3v, g3, 72, t);   cp_sm(sm.be3v, be3, 72, t); cp_sm(sm.a3v, a3, 72, t);
    cp_sm(sm.embs, emb, 3 * 18, t);

    // ---- analytic hex topology ----
    int nbU[6];
    float dnb[6];
    float disn = 0.f;
    if (isNode) {
        const int r = t / NBOARD, c = t % NBOARD;
        const int drr[6] = { -1, 1, 0, 0, -1, 1 };
        const int dcc[6] = { 0, 0, -1, 1, 1, -1 };
        int deg = 1;
        #pragma unroll
        for (int j = 0; j < 6; j++) {
            int rr = r + drr[j], cc = c + dcc[j];
            if (rr >= 0 && rr < NBOARD && cc >= 0 && cc < NBOARD) {
                nbU[j] = (rr * NBOARD + cc) * HSU;
                deg++;
            } else {
                nbU[j] = t * HSU;
            }
        }
        disn = rsqrtf((float)deg);
        sm.dis[t] = disn;
    }
    __syncthreads();

    if (isNode) {
        const int xv = x[g * SN + t];
        #pragma unroll
        for (int k = 0; k < 18; k++) sm.h[t * HS + k] = sm.embs[xv * 18 + k];
        #pragma unroll
        for (int j = 0; j < 6; j++)
            dnb[j] = (nbU[j] == t * HSU) ? 0.f : sm.dis[nbU[j] / HSU];
    }
    __syncthreads();

    const ull dd = pk2(disn, disn);

    // ================= Layer 1: SGConv(18->18) + GN + identity residual =====
    {
        ull hkU[9], aU[9], accC[9];
        if (isNode) {
            const ull* hr = hU + t * HSU;
            #pragma unroll
            for (int i = 0; i < 9; i++) { hkU[i] = hr[i]; aU[i] = fmul2(hkU[i], dd); }
            #pragma unroll
            for (int j = 0; j < 6; j++) {
                const ull* p = hU + nbU[j];
                const ull wj = pk2(dnb[j], dnb[j]);
                #pragma unroll
                for (int i = 0; i < 9; i++) aU[i] = ffma2(wj, p[i], aU[i]);
            }
            #pragma unroll
            for (int i = 0; i < 9; i++) aU[i] = fmul2(aU[i], dd);
            const ull* bu = (const ull*)sm.bc1;
            #pragma unroll
            for (int i = 0; i < 9; i++) accC[i] = bu[i];
            #pragma unroll 2
            for (int kp = 0; kp < 9; kp++) {
                float2 av = upk2(aU[kp]);
                #pragma unroll
                for (int s = 0; s < 2; s++) {
                    const float ak = s ? av.y : av.x;
                    const ull aa = pk2(ak, ak);
                    const float* wrow = &sm.wc1p[(2 * kp + s) * 20];
                    const ulonglong2* w2 = (const ulonglong2*)wrow;
                    #pragma unroll
                    for (int jv = 0; jv < 4; jv++) {
                        ulonglong2 w = w2[jv];
                        accC[2 * jv]     = ffma2(aa, w.x, accC[2 * jv]);
                        accC[2 * jv + 1] = ffma2(aa, w.y, accC[2 * jv + 1]);
                    }
                    accC[8] = ffma2(aa, ((const ull*)wrow)[8], accC[8]);
                }
            }
            ull* st = stU + t * TSU;
            #pragma unroll
            for (int i = 0; i < 9; i++) st[i] = accC[i];
        }
        __syncthreads();
        stats_striped(sm, t, 18);
        __syncthreads();
        if (t < 18) {
            float s = 0.f, s2 = 0.f;
            #pragma unroll
            for (int i = 0; i < 10; i++) { s += sm.redP[t + i * 18]; s2 += sm.redQ[t + i * 18]; }
            float m = s * invS;
            float af = sm.a1v[t];
            float var = s2 * invS - m * m * af * (2.0f - af);
            float S = sm.g1v[t] * rsqrtf(var + EPSV);
            sm.redS[t] = S; sm.redC[t] = sm.be1v[t] - af * m * S;
        }
        __syncthreads();
        if (isNode) {
            const ull* Su = (const ull*)sm.redS;
            const ull* Cu = (const ull*)sm.redC;
            ull* hr = hU + t * HSU;
            #pragma unroll
            for (int i = 0; i < 9; i++)
                hr[i] = fadd2(ffma2(accC[i], Su[i], Cu[i]), hkU[i]);
        }
        __syncthreads();
    }

    // ====== Layer 2: gather -> resid pass (into h) -> conv pass -> GN =======
    {
        ull hkU[9], aU[9];
        if (isNode) {
            const ull* hr = hU + t * HSU;
            #pragma unroll
            for (int i = 0; i < 9; i++) { hkU[i] = hr[i]; aU[i] = fmul2(hkU[i], dd); }
            #pragma unroll
            for (int j = 0; j < 6; j++) {
                const ull* p = hU + nbU[j];
                const ull wj = pk2(dnb[j], dnb[j]);
                #pragma unroll
                for (int i = 0; i < 9; i++) aU[i] = ffma2(wj, p[i], aU[i]);
            }
            #pragma unroll
            for (int i = 0; i < 9; i++) aU[i] = fmul2(aU[i], dd);
        }
        __syncthreads();   // gathers complete before h is overwritten

        if (isNode) {
            // residual proj 18->36 into h
            ull accR[18];
            const ull* buR = (const ull*)sm.br1;
            #pragma unroll
            for (int i = 0; i < 18; i++) accR[i] = buR[i];
            #pragma unroll 2
            for (int kp = 0; kp < 9; kp++) {
                float2 hv = upk2(hkU[kp]);
                #pragma unroll
                for (int s = 0; s < 2; s++) {
                    const float hk = s ? hv.y : hv.x;
                    const ull hh = pk2(hk, hk);
                    const ulonglong2* wr = (const ulonglong2*)&sm.wr1[(2 * kp + s) * 36];
                    #pragma unroll
                    for (int jv = 0; jv < 9; jv++) {
                        ulonglong2 u = wr[jv];
                        accR[2 * jv]     = ffma2(hh, u.x, accR[2 * jv]);
                        accR[2 * jv + 1] = ffma2(hh, u.y, accR[2 * jv + 1]);
                    }
                }
            }
            ull* hr = hU + t * HSU;
            #pragma unroll
            for (int i = 0; i < 18; i++) hr[i] = accR[i];
        }

        // conv 18->36
        ull accC[18];
        if (isNode) {
            const ull* buC = (const ull*)sm.bc2;
            #pragma unroll
            for (int i = 0; i < 18; i++) accC[i] = buC[i];
            #pragma unroll 2
            for (int kp = 0; kp < 9; kp++) {
                float2 av = upk2(aU[kp]);
                #pragma unroll
                for (int s = 0; s < 2; s++) {
                    const float ak = s ? av.y : av.x;
                    const ull aa = pk2(ak, ak);
                    const ulonglong2* wc = (const ulonglong2*)&sm.wc2[(2 * kp + s) * 36];
                    #pragma unroll
                    for (int jv = 0; jv < 9; jv++) {
                        ulonglong2 w = wc[jv];
                        accC[2 * jv]     = ffma2(aa, w.x, accC[2 * jv]);
                        accC[2 * jv + 1] = ffma2(aa, w.y, accC[2 * jv + 1]);
                    }
                }
            }
            ull* st = stU + t * TSU;
            #pragma unroll
            for (int i = 0; i < 18; i++) st[i] = accC[i];
        }
        __syncthreads();
        stats_striped(sm, t, 36);
        __syncthreads();
        if (t < 36) {
            float s = 0.f, s2 = 0.f;
            #pragma unroll
            for (int i = 0; i < 5; i++) { s += sm.redP[t + i * 36]; s2 += sm.redQ[t + i * 36]; }
            float m = s * invS;
            float af = sm.a2v[t];
            float var = s2 * invS - m * m * af * (2.0f - af);
            float S = sm.g2v[t] * rsqrtf(var + EPSV);
            sm.redS[t] = S; sm.redC[t] = sm.be2v[t] - af * m * S;
        }
        __syncthreads();
        if (isNode) {
            const ull* Su = (const ull*)sm.redS;
            const ull* Cu = (const ull*)sm.redC;
            ull* hr = hU + t * HSU;
            #pragma unroll
            for (int i = 0; i < 18; i++)
                hr[i] = fadd2(ffma2(accC[i], Su[i], Cu[i]), hr[i]);
        }
        __syncthreads();
    }

    // ====== Layer 3: gather -> resid (2 halves into h) -> conv per half =====
    {
        ull hkU[18], aU[18];
        if (isNode) {
            const ull* hr = hU + t * HSU;
            #pragma unroll
            for (int i = 0; i < 18; i++) { hkU[i] = hr[i]; aU[i] = fmul2(hkU[i], dd); }
            #pragma unroll
            for (int j = 0; j < 6; j++) {
                const ull* p = hU + nbU[j];
                const ull wj = pk2(dnb[j], dnb[j]);
                #pragma unroll
                for (int i = 0; i < 18; i++) aU[i] = ffma2(wj, p[i], aU[i]);
            }
            #pragma unroll
            for (int i = 0; i < 18; i++) aU[i] = fmul2(aU[i], dd);
        }
        __syncthreads();

        if (isNode) {
            #pragma unroll
            for (int half = 0; half < 2; half++) {
                ull accR[18];
                const ull* buR = (const ull*)&sm.br2[half * 36];
                #pragma unroll
                for (int i = 0; i < 18; i++) accR[i] = buR[i];
                #pragma unroll 1
                for (int kp = 0; kp < 18; kp++) {
                    float2 hv = upk2(hkU[kp]);
                    #pragma unroll
                    for (int s = 0; s < 2; s++) {
                        const float hk = s ? hv.y : hv.x;
                        const ull hh = pk2(hk, hk);
                        const ulonglong2* wr = (const ulonglong2*)&sm.wr2[(2 * kp + s) * 72 + half * 36];
                        #pragma unroll
                        for (int jv = 0; jv < 9; jv++) {
                            ulonglong2 u = wr[jv];
                            accR[2 * jv]     = ffma2(hh, u.x, accR[2 * jv]);
                            accR[2 * jv + 1] = ffma2(hh, u.y, accR[2 * jv + 1]);
                        }
                    }
                }
                ull* hr = hU + t * HSU + half * 18;
                #pragma unroll
                for (int i = 0; i < 18; i++) hr[i] = accR[i];
            }
        }

        // conv per half: accC[18] live only inside the half
        #pragma unroll
        for (int half = 0; half < 2; half++) {
            ull accC[18];
            if (isNode) {
                const ull* buC = (const ull*)&sm.bc3[half * 36];
                #pragma unroll
                for (int i = 0; i < 18; i++) accC[i] = buC[i];
                #pragma unroll 1
                for (int kp = 0; kp < 18; kp++) {
                    float2 av = upk2(aU[kp]);
                    #pragma unroll
                    for (int s = 0; s < 2; s++) {
                        const float ak = s ? av.y : av.x;
                        const ull aa = pk2(ak, ak);
                        const ulonglong2* wc = (const ulonglong2*)&sm.wc3[(2 * kp + s) * 72 + half * 36];
                        #pragma unroll
                        for (int jv = 0; jv < 9; jv++) {
                            ulonglong2 w = wc[jv];
                            accC[2 * jv]     = ffma2(aa, w.x, accC[2 * jv]);
                            accC[2 * jv + 1] = ffma2(aa, w.y, accC[2 * jv + 1]);
                        }
                    }
                }
                ull* st = stU + t * TSU;
                #pragma unroll
                for (int i = 0; i < 18; i++) st[i] = accC[i];
            }
            __syncthreads();
            stats_striped(sm, t, 36);
            __syncthreads();
            if (t < 36) {
                float s = 0.f, s2 = 0.f;
                #pragma unroll
                for (int i = 0; i < 5; i++) { s += sm.redP[t + i * 36]; s2 += sm.redQ[t + i * 36]; }
                const int fg = half * 36 + t;
                float m = s * invS;
                float af = sm.a3v[fg];
                float var = s2 * invS - m * m * af * (2.0f - af);
                float S = sm.g3v[fg] * rsqrtf(var + EPSV);
                sm.redS[fg] = S; sm.redC[fg] = sm.be3v[fg] - af * m * S;
            }
            __syncthreads();
            if (isNode) {
                const ull* Su = (const ull*)&sm.redS[half * 36];
                const ull* Cu = (const ull*)&sm.redC[half * 36];
                ull* hr = hU + t * HSU + half * 18;
                #pragma unroll
                for (int i = 0; i < 18; i++)
                    hr[i] = fadd2(ffma2(accC[i], Su[i], Cu[i]), hr[i]);
            }
            __syncthreads();
        }
    }

    // ---- striped max pool ----
    if (t < 144) {
        const int f = t % 72, sI = t / 72;
        float m = -INFINITY;
        const float* p = sm.h + f;
        for (int n = sI; n < SN; n += 2) m = fmaxf(m, p[n * HS]);
        sm.redP[t] = m;
    }
    __syncthreads();
    if (t < 72) g_pooled[g * 72 + t] = fmaxf(sm.redP[t], sm.redP[t + 72]);
}

// ---------------------------------------------------------------------------
// MLP (unchanged from round 3: 36 µs)
// ---------------------------------------------------------------------------
struct __align__(16) MSmem {
    ull rowsT[72][5];
    ull z1T[512][5];
    ull z2P[256][5];
    ull z2T[256][5];
};

__global__ void __launch_bounds__(512, 2) mlp_kernel(
    const float* __restrict__ wf1, const float* __restrict__ bf1,
    const float* __restrict__ wf2, const float* __restrict__ bf2,
    const float* __restrict__ wm, const float* __restrict__ bm,
    const float* __restrict__ wl, const float* __restrict__ bl,
    float* __restrict__ out)
{
    extern __shared__ char smraw[];
    MSmem& sm = *reinterpret_cast<MSmem*>(smraw);
    const int tid = threadIdx.x;
    const int r0 = blockIdx.x * 8;

    {
        float* rf = (float*)sm.rowsT;
        for (int i = tid; i < 8 * 72; i += 512) {
            const int k = i / 8, r = i % 8;
            rf[k * 10 + r] = g_pooled[(r0 + r) * 72 + k];
        }
    }
    __syncthreads();

    {
        const int j = tid;
        const float b = __ldg(bf1 + j);
        ull acc[4];
        #pragma unroll
        for (int i = 0; i < 4; i++) acc[i] = pk2(b, b);
        #pragma unroll 8
        for (int k = 0; k < 72; k++) {
            const float w = __ldg(wf1 + k * 512 + j);
            const ull ww = pk2(w, w);
            const ull* rw = sm.rowsT[k];
            #pragma unroll
            for (int i = 0; i < 4; i++) acc[i] = ffma2(ww, rw[i], acc[i]);
        }
        #pragma unroll
        for (int i = 0; i < 4; i++) {
            float2 v = upk2(acc[i]);
            sm.z1T[j][i] = pk2(fmaxf(v.x, 0.f), fmaxf(v.y, 0.f));
        }
    }
    __syncthreads();

    {
        const int jj = tid & 255, half = tid >> 8;
        ull acc[4];
        if (half == 0) {
            const float b = __ldg(bf2 + jj);
            #pragma unroll
            for (int i = 0; i < 4; i++) acc[i] = pk2(b, b);
        } else {
            #pragma unroll
            for (int i = 0; i < 4; i++) acc[i] = 0ull;
        }
        const int k0 = half * 256;
        #pragma unroll 8
        for (int kk = 0; kk < 256; kk++) {
            const int k = k0 + kk;
            const float w = __ldg(wf2 + k * 256 + jj);
            const ull ww = pk2(w, w);
            const ull* zw = sm.z1T[k];
            #pragma unroll
            for (int i = 0; i < 4; i++) acc[i] = ffma2(ww, zw[i], acc[i]);
        }
        if (half == 1) {
            #pragma unroll
            for (int i = 0; i < 4; i++) sm.z2P[jj][i] = acc[i];
        }
        __syncthreads();
        if (half == 0) {
            #pragma unroll
            for (int i = 0; i < 4; i++) {
                float2 v = upk2(fadd2(acc[i], sm.z2P[jj][i]));
                sm.z2T[jj][i] = pk2(fmaxf(v.x, 0.f), fmaxf(v.y, 0.f));
            }
        }
        __syncthreads();
    }

    {
        const int w = tid >> 5, lane = tid & 31;
        if (w < 8) {
            const int rp = w >> 1, hi = w & 1;
            float smv = 0.f, slv = 0.f;
            #pragma unroll 4
            for (int k = lane; k < 256; k += 32) {
                float2 v2 = upk2(sm.z2T[k][rp]);
                const float v = hi ? v2.y : v2.x;
                smv = fmaf(v, __ldg(wm + k), smv);
                slv = fmaf(v, __ldg(wl + k), slv);
            }
            #pragma unroll
            for (int o = 16; o > 0; o >>= 1) {
                smv += __shfl_xor_sync(0xffffffffu, smv, o);
                slv += __shfl_xor_sync(0xffffffffu, slv, o);
            }
            if (lane == 0) {
                out[r0 + w] = smv + __ldg(bm);
                const float ls = tanhf(slv + __ldg(bl));
                out[NG + r0 + w] = LSMIN + 0.5f * (LSMAX - LSMIN) * (ls + 1.0f);
            }
        }
    }
}

// ---------------------------------------------------------------------------
extern "C" void kernel_launch(void* const* d_in, const int* in_sizes, int n_in,
                              void* d_out, int out_size)
{
    const int*   x    = (const int*)d_in[0];
    const float* emb  = (const float*)d_in[2];
    const float* wc1  = (const float*)d_in[3];
    const float* bc1  = (const float*)d_in[4];
    const float* wc2  = (const float*)d_in[5];
    const float* bc2  = (const float*)d_in[6];
    const float* wc3  = (const float*)d_in[7];
    const float* bc3  = (const float*)d_in[8];
    const float* wr1  = (const float*)d_in[9];
    const float* br1  = (const float*)d_in[10];
    const float* wr2  = (const float*)d_in[11];
    const float* br2  = (const float*)d_in[12];
    const float* g1   = (const float*)d_in[13];
    const float* be1  = (const float*)d_in[14];
    const float* a1   = (const float*)d_in[15];
    const float* g2   = (const float*)d_in[16];
    const float* be2  = (const float*)d_in[17];
    const float* a2   = (const float*)d_in[18];
    const float* g3   = (const float*)d_in[19];
    const float* be3  = (const float*)d_in[20];
    const float* a3   = (const float*)d_in[21];
    const float* wf1  = (const float*)d_in[22];
    const float* bf1  = (const float*)d_in[23];
    const float* wf2  = (const float*)d_in[24];
    const float* bf2  = (const float*)d_in[25];
    const float* wm   = (const float*)d_in[26];
    const float* bm   = (const float*)d_in[27];
    const float* wl   = (const float*)d_in[28];
    const float* bl   = (const float*)d_in[29];
    float* out = (float*)d_out;

    cudaFuncSetAttribute(gnn_kernel, cudaFuncAttributeMaxDynamicSharedMemorySize,
                         (int)sizeof(Smem));
    cudaFuncSetAttribute(mlp_kernel, cudaFuncAttributeMaxDynamicSharedMemorySize,
                         (int)sizeof(MSmem));

    gnn_kernel<<<NG, NT, sizeof(Smem)>>>(
        x, emb, wc1, bc1, wc2, bc2, wc3, bc3, wr1, br1, wr2, br2,
        g1, be1, a1, g2, be2, a2, g3, be3, a3);

    mlp_kernel<<<NG / 8, 512, sizeof(MSmem)>>>(
        wf1, bf1, wf2, bf2, wm, bm, wl, bl, out);
}